// round 10
// baseline (speedup 1.0000x reference)
#include <cuda_runtime.h>
#include <math.h>

#define NB 16
#define NP 32768
#define NG 32
#define NC 81
#define TPB 128                        // threads per block = rows per block
#define BPI (NP / TPB)                 // 256 blocks per image
#define MAIN_BLOCKS (NB * BPI)         // 4096
#define NV4 (TPB * NC / 4)             // 2592 float4 per tile
#define NBINH 16384                    // histogram bins per image
#define BIN_BASE 0x3C000000            // float bits of 2^-7 (< 1/81)
#define BIN_SHIFT 12
#define LIST_CAP 2048
#define BINS_PER_T (NBINH / TPB)       // 128 bins per thread in select phase

// Scratch (device globals; no allocation allowed). All counters self-reset.
__device__ float    g_neg[NB * NP];      // 0 if row matched, else sm_max
__device__ unsigned g_hist[NB * NBINH];  // per-image value histogram
__device__ float    g_pm[MAIN_BLOCKS];
__device__ float    g_pl[MAIN_BLOCKS];
__device__ int      g_pt[MAIN_BLOCKS];
__device__ float    g_res[NB];
__device__ float    g_tot[NB];
__device__ unsigned g_done[NB];          // per-image completion counters
__device__ unsigned g_ctr = 0;           // image-level counter

static __device__ __forceinline__ float warp_sum(float v) {
    #pragma unroll
    for (int o = 16; o; o >>= 1) v += __shfl_xor_sync(0xffffffffu, v, o);
    return v;
}
static __device__ __forceinline__ void warp_sum2(float& a, float& b) {
    #pragma unroll
    for (int o = 16; o; o >>= 1) {
        float aa = __shfl_xor_sync(0xffffffffu, a, o);
        float bb = __shfl_xor_sync(0xffffffffu, b, o);
        a += aa; b += bb;
    }
}
static __device__ __forceinline__ int val_bin(float v) {
    int bin = ((int)__float_as_uint(v) - BIN_BASE) >> BIN_SHIFT;
    return bin < 0 ? 0 : (bin > NBINH - 1 ? NBINH - 1 : bin);
}

// Fused kernel: per-block main work (row-per-thread over a cp.async-staged conf
// tile); the last block to finish an image runs that image's select inline;
// the last image's selector writes the final scalar.
__global__ __launch_bounds__(TPB) void fused_kernel(
    const float4* __restrict__ pboxes,   // (B,P,4)
    const float*  __restrict__ conf,     // (B,P,C)
    const float4* __restrict__ gboxes,   // (B,G,4)
    const int*    __restrict__ glab,     // (B,G)
    float* __restrict__ out)
{
    __shared__ float  s_conf[TPB * NC];  // 41472 B (aliased as s_list in select)
    __shared__ float4 s_g[NG];
    __shared__ float  s_ga[NG];
    __shared__ int    s_gl[NG];
    __shared__ float  s_ra[4], s_rb[4];
    __shared__ int    s_rt[4];
    __shared__ int    s_sel, s_fin;
    __shared__ float  s_M, s_L;
    __shared__ int    s_k, s_D;
    __shared__ unsigned s_krem, s_cnt;
    __shared__ unsigned s_wsum[4], s_wabove[4];

    const int tid  = threadIdx.x;
    const int lane = tid & 31, warp = tid >> 5;
    const int b    = blockIdx.x / BPI;

    // ---- stage conf tile with cp.async: all ~20 loads/thread in flight ----
    {
        const char* src = (const char*)conf + (size_t)blockIdx.x * (TPB * NC * 4);
        unsigned sbase = (unsigned)__cvta_generic_to_shared(s_conf);
        for (int i = tid; i < NV4; i += TPB) {
            unsigned daddr = sbase + i * 16;
            asm volatile("cp.async.cg.shared.global [%0], [%1], 16;"
                         :: "r"(daddr), "l"(src + (size_t)i * 16));
        }
        asm volatile("cp.async.commit_group;");
    }

    if (tid < NG) {
        float4 g = gboxes[b * NG + tid];
        s_g[tid]  = g;
        s_ga[tid] = fmaxf(g.z - g.x, 0.f) * fmaxf(g.w - g.y, 0.f);
        s_gl[tid] = glab[b * NG + tid];
    }

    asm volatile("cp.async.wait_group 0;" ::: "memory");
    __syncthreads();

    const int row = blockIdx.x * TPB + tid;
    const float* r = s_conf + tid * NC;         // stride 81: conflict-free

    // raw-exp softmax stats with 4-way ILP (conf ~ N(0,1): safe in fp32)
    float s0 = 0.f, s1 = 0.f, s2 = 0.f, s3 = 0.f;
    float m0 = -1e30f, m1 = -1e30f, m2 = -1e30f, m3 = -1e30f;
    #pragma unroll
    for (int c = 0; c < 80; c += 4) {
        float x0 = r[c], x1 = r[c + 1], x2 = r[c + 2], x3 = r[c + 3];
        s0 += __expf(x0); s1 += __expf(x1); s2 += __expf(x2); s3 += __expf(x3);
        m0 = fmaxf(m0, x0); m1 = fmaxf(m1, x1); m2 = fmaxf(m2, x2); m3 = fmaxf(m3, x3);
    }
    { float x = r[80]; s0 += __expf(x); m0 = fmaxf(m0, x); }
    float ssum = (s0 + s1) + (s2 + s3);
    float mmax = fmaxf(fmaxf(m0, m1), fmaxf(m2, m3));
    float lse   = __logf(ssum);
    float smmax = __fdividef(__expf(mmax), ssum);

    // IoU vs 32 gt boxes
    float4 pb = pboxes[row];
    float pa = fmaxf(pb.z - pb.x, 0.f) * fmaxf(pb.w - pb.y, 0.f);
    float mc = 0.f, lc = 0.f;
    int   tc = 0;
    bool  any = false;
    #pragma unroll 4
    for (int g = 0; g < NG; ++g) {
        float4 gb = s_g[g];
        float ltx = fmaxf(pb.x, gb.x), lty = fmaxf(pb.y, gb.y);
        float rbx = fminf(pb.z, gb.z), rby = fminf(pb.w, gb.w);
        float inter = fmaxf(rbx - ltx, 0.f) * fmaxf(rby - lty, 0.f);
        float uni = pa + s_ga[g] - inter;
        if (inter > 0.5f * fmaxf(uni, 1e-9f)) {
            any = true; ++tc;
            mc += r[s_gl[g]] - lse;
            float sl = 0.f, d, ad;
            d = pb.x - gb.x; ad = fabsf(d); sl += (ad < 1.f) ? 0.5f * d * d : ad - 0.5f;
            d = pb.y - gb.y; ad = fabsf(d); sl += (ad < 1.f) ? 0.5f * d * d : ad - 0.5f;
            d = pb.z - gb.z; ad = fabsf(d); sl += (ad < 1.f) ? 0.5f * d * d : ad - 0.5f;
            d = pb.w - gb.w; ad = fabsf(d); sl += (ad < 1.f) ? 0.5f * d * d : ad - 0.5f;
            lc += sl * 0.25f;
        }
    }

    float myneg = any ? 0.f : smmax;
    g_neg[row] = myneg;
    atomicAdd(&g_hist[b * NBINH + val_bin(myneg)], 1u);

    // block partials
    warp_sum2(mc, lc);
    unsigned tcu = __reduce_add_sync(0xffffffffu, (unsigned)tc);
    if (lane == 0) { s_ra[warp] = mc; s_rb[warp] = lc; s_rt[warp] = (int)tcu; }

    // every thread fences its own g_neg/g_hist writes BEFORE the done-counter
    __threadfence();
    __syncthreads();
    if (tid == 0) {
        float M = 0.f, L = 0.f; int T = 0;
        #pragma unroll
        for (int w = 0; w < 4; ++w) { M += s_ra[w]; L += s_rb[w]; T += s_rt[w]; }
        g_pm[blockIdx.x] = M; g_pl[blockIdx.x] = L; g_pt[blockIdx.x] = T;
        __threadfence();
        unsigned old = atomicAdd(&g_done[b], 1u);
        s_sel = (old == BPI - 1) ? 1 : 0;
        if (s_sel) g_done[b] = 0u;              // reset for next replay
    }
    __syncthreads();
    if (!s_sel) return;

    // ================= SELECT PHASE (one block per image) =================
    __threadfence();                            // see other blocks' writes

    // reduce this image's 256 partials (2 per thread)
    float pm = 0.f, pl = 0.f; unsigned pt = 0u;
    for (int i = b * BPI + tid; i < (b + 1) * BPI; i += TPB) {
        pm += g_pm[i]; pl += g_pl[i]; pt += (unsigned)g_pt[i];
    }
    warp_sum2(pm, pl);
    pt = __reduce_add_sync(0xffffffffu, pt);
    if (lane == 0) { s_ra[warp] = pm; s_rb[warp] = pl; s_rt[warp] = (int)pt; }
    if (tid == 0) { s_cnt = 0u; s_D = -1; s_krem = 0u; }
    __syncthreads();
    if (tid == 0) {
        float M = 0.f, L = 0.f; int T = 0;
        #pragma unroll
        for (int w = 0; w < 4; ++w) { M += s_ra[w]; L += s_rb[w]; T += s_rt[w]; }
        s_M = M; s_L = L;
        int k = 3 * T;
        if (k > NP) k = NP;
        s_k = k;
        g_tot[b] = (float)T;
    }
    __syncthreads();

    const unsigned k = (unsigned)s_k;
    unsigned* hist = g_hist + (size_t)b * NBINH;

    // per-thread chunk sum (128 bins), then 128-thread suffix-scan from the top
    unsigned part = 0u;
    {
        const uint4* hb = (const uint4*)hist;
        #pragma unroll
        for (int j = 0; j < BINS_PER_T / 4; ++j) {
            uint4 v = hb[tid * (BINS_PER_T / 4) + j];
            part += v.x + v.y + v.z + v.w;
        }
    }
    unsigned incl = part;                       // suffix-incl within warp
    #pragma unroll
    for (int o = 1; o < 32; o <<= 1) {
        unsigned n = __shfl_down_sync(0xffffffffu, incl, o);
        if (lane + o < 32) incl += n;
    }
    if (lane == 0) s_wsum[warp] = incl;
    __syncthreads();
    if (tid == 0) {
        s_wabove[3] = 0u;
        s_wabove[2] = s_wsum[3];
        s_wabove[1] = s_wsum[2] + s_wsum[3];
        s_wabove[0] = s_wsum[1] + s_wsum[2] + s_wsum[3];
    }
    __syncthreads();

    if (k > 0) {
        unsigned above = s_wabove[warp] + (incl - part);
        if (above < k && above + part >= k) {   // unique boundary chunk
            unsigned cum = above;
            int base = tid * BINS_PER_T;
            for (int j = BINS_PER_T - 1; j >= 0; --j) {
                unsigned c = hist[base + j];
                if (cum + c >= k) { s_D = base + j; s_krem = k - cum; break; }
                cum += c;
            }
        }
    }
    __syncthreads();

    const int      D    = s_D;
    const unsigned krem = s_krem;

    // reset own hist chunk (disjoint per thread; only own chunk was read)
    {
        uint4 z = make_uint4(0u, 0u, 0u, 0u);
        uint4* hw = (uint4*)hist;
        #pragma unroll
        for (int j = 0; j < BINS_PER_T / 4; ++j) hw[tid * (BINS_PER_T / 4) + j] = z;
    }

    float* s_list = s_conf;                     // alias dead tile memory

    // single sweep: bulk log1p for bins > D, collect boundary-bin values
    float local = 0.f;
    if (k > 0) {
        const float4* v4p = (const float4*)(g_neg + (size_t)b * NP);
        for (int i = tid; i < NP / 4; i += TPB) {
            float4 v4 = v4p[i];
            #pragma unroll
            for (int c = 0; c < 4; ++c) {
                float v = (c == 0) ? v4.x : (c == 1) ? v4.y : (c == 2) ? v4.z : v4.w;
                int bin = val_bin(v);
                if (bin > D) local += log1pf(v);
                else if (bin == D) {
                    unsigned idx = atomicAdd(&s_cnt, 1u);
                    if (idx < LIST_CAP) s_list[idx] = v;
                }
            }
        }
    }
    __syncthreads();

    // exact rank-select of krem largest within the boundary bin
    if (k > 0) {
        int L = (int)(s_cnt < LIST_CAP ? s_cnt : LIST_CAP);
        for (int j = tid; j < L; j += TPB) {
            float vj = s_list[j];
            int G = 0, E = 0;
            for (int i = 0; i < L; ++i) {
                float vi = s_list[i];
                G += (vi > vj);
                E += (vi == vj && i < j);
            }
            if ((unsigned)(G + E) < krem) local += log1pf(vj);
        }
    }

    local = warp_sum(local);
    if (lane == 0) s_ra[warp] = local;
    __syncthreads();
    if (tid == 0) {
        float nm = s_ra[0] + s_ra[1] + s_ra[2] + s_ra[3];
        g_res[b] = nm - s_M + s_L;
        __threadfence();
        unsigned old = atomicAdd(&g_ctr, 1u);
        s_fin = (old == NB - 1) ? 1 : 0;
        if (s_fin) g_ctr = 0u;                  // reset for next replay
    }
    __syncthreads();

    // last image's selector folds the 16 per-image results
    if (s_fin && warp == 0) {
        __threadfence();
        float v = (lane < NB) ? g_res[lane] : 0.f;
        v = warp_sum(v);
        if (lane == 0) out[0] = v / g_tot[NB - 1];
    }
}

extern "C" void kernel_launch(void* const* d_in, const int* in_sizes, int n_in,
                              void* d_out, int out_size)
{
    const float4* pboxes = (const float4*)d_in[0];
    const float*  conf   = (const float*)d_in[1];
    const float4* gboxes = (const float4*)d_in[2];
    const int*    glab   = (const int*)d_in[3];

    fused_kernel<<<MAIN_BLOCKS, TPB>>>(pboxes, conf, gboxes, glab, (float*)d_out);
}

// round 13
// speedup vs baseline: 1.3146x; 1.3146x over previous
#include <cuda_runtime.h>
#include <math.h>

#define NB 16
#define NP 32768
#define NG 32
#define NC 81
#define TPB 128                         // threads per main block
#define TILE_ROWS 128                   // rows per tile (= TPB, row per thread)
#define NTILES (NB * NP / TILE_ROWS)    // 4096
#define TILES_PER_IMG (NP / TILE_ROWS)  // 256
#define GRID 296                        // 2 blocks per SM on 148 SMs
#define TILE_F4 (TILE_ROWS * NC / 4)    // 2592 float4 per tile
#define TILE_BYTES (TILE_ROWS * NC * 4) // 41472
#define NBINH 16384
#define BIN_BASE 0x3C000000             // float bits of 2^-7 (< 1/81)
#define BIN_SHIFT 12
#define LIST_CAP 2048
#define BINS_PER_T 16                   // bins/thread in 1024-thread select

// Scratch (device globals). All accumulators/counters self-reset each run.
__device__ float    g_neg[NB * NP];     // 0 if row matched, else sm_max
__device__ unsigned g_hist[NB * NBINH]; // per-image histogram
__device__ float    g_pm[NB];           // per-image matches_loss (RED-accumulated)
__device__ float    g_pl[NB];           // per-image loc_loss
__device__ int      g_pt[NB];           // per-image total
__device__ float    g_res[NB];
__device__ float    g_tot[NB];
__device__ unsigned g_ctr = 0;

static __device__ __forceinline__ float warp_sum(float v) {
    #pragma unroll
    for (int o = 16; o; o >>= 1) v += __shfl_xor_sync(0xffffffffu, v, o);
    return v;
}
static __device__ __forceinline__ void warp_sum2(float& a, float& b) {
    #pragma unroll
    for (int o = 16; o; o >>= 1) {
        float aa = __shfl_xor_sync(0xffffffffu, a, o);
        float bb = __shfl_xor_sync(0xffffffffu, b, o);
        a += aa; b += bb;
    }
}
static __device__ __forceinline__ int val_bin(float v) {
    int bin = ((int)__float_as_uint(v) - BIN_BASE) >> BIN_SHIFT;
    return bin < 0 ? 0 : (bin > NBINH - 1 ? NBINH - 1 : bin);
}

// Double-buffered streaming main kernel. 296 blocks grid-stride over 4096
// tiles; cp.async prefetches tile t+GRID into the spare buffer while tile t
// is computed, keeping DRAM busy through compute.
__global__ __launch_bounds__(TPB) void main_kernel(
    const float4* __restrict__ pboxes,   // (B,P,4)
    const float*  __restrict__ conf,     // (B,P,C)
    const float4* __restrict__ gboxes,   // (B,G,4)
    const int*    __restrict__ glab)     // (B,G)
{
    extern __shared__ float s_buf[];     // 2 * TILE_F4 float4 = 82944 B
    __shared__ float4 s_g[NG];
    __shared__ float  s_ga[NG];
    __shared__ int    s_gl[NG];
    __shared__ float  s_ra[4], s_rb[4];
    __shared__ int    s_rt[4];

    const int tid  = threadIdx.x;
    const int lane = tid & 31, warp = tid >> 5;

    const unsigned sb0 = (unsigned)__cvta_generic_to_shared(s_buf);
    #define CP_LOAD(t, bufi)                                                    \
        do {                                                                    \
            const char* _src = (const char*)conf + (size_t)(t) * TILE_BYTES;    \
            unsigned _dst = sb0 + (bufi) * TILE_BYTES;                          \
            for (int _i = tid; _i < TILE_F4; _i += TPB)                         \
                asm volatile("cp.async.cg.shared.global [%0], [%1], 16;"        \
                             :: "r"(_dst + _i * 16), "l"(_src + (size_t)_i * 16)); \
            asm volatile("cp.async.commit_group;");                             \
        } while (0)

    int t   = blockIdx.x;
    int cur = 0;
    CP_LOAD(t, 0);

    while (t < NTILES) {
        const int tn = t + GRID;
        if (tn < NTILES) {
            CP_LOAD(tn, cur ^ 1);
            asm volatile("cp.async.wait_group 1;" ::: "memory");
        } else {
            asm volatile("cp.async.wait_group 0;" ::: "memory");
        }

        const int b = t / TILES_PER_IMG;
        if (tid < NG) {                  // (re)load gt data for this image
            float4 g = gboxes[b * NG + tid];
            s_g[tid]  = g;
            s_ga[tid] = fmaxf(g.z - g.x, 0.f) * fmaxf(g.w - g.y, 0.f);
            s_gl[tid] = glab[b * NG + tid];
        }
        __syncthreads();

        const int row = t * TILE_ROWS + tid;
        const float* r = s_buf + cur * (TILE_F4 * 4) + tid * NC;

        // raw-exp softmax stats, 4-way ILP (conf ~ N(0,1): safe in fp32)
        float s0 = 0.f, s1 = 0.f, s2 = 0.f, s3 = 0.f;
        float m0 = -1e30f, m1 = -1e30f, m2 = -1e30f, m3 = -1e30f;
        #pragma unroll
        for (int c = 0; c < 80; c += 4) {
            float x0 = r[c], x1 = r[c + 1], x2 = r[c + 2], x3 = r[c + 3];
            s0 += __expf(x0); s1 += __expf(x1); s2 += __expf(x2); s3 += __expf(x3);
            m0 = fmaxf(m0, x0); m1 = fmaxf(m1, x1);
            m2 = fmaxf(m2, x2); m3 = fmaxf(m3, x3);
        }
        { float x = r[80]; s0 += __expf(x); m0 = fmaxf(m0, x); }
        float ssum = (s0 + s1) + (s2 + s3);
        float mmax = fmaxf(fmaxf(m0, m1), fmaxf(m2, m3));
        float lse   = __logf(ssum);
        float smmax = __fdividef(__expf(mmax), ssum);

        // IoU vs 32 gt boxes
        float4 pb = pboxes[row];
        float pa = fmaxf(pb.z - pb.x, 0.f) * fmaxf(pb.w - pb.y, 0.f);
        float mc = 0.f, lc = 0.f;
        int   tc = 0;
        bool  any = false;
        #pragma unroll 4
        for (int g = 0; g < NG; ++g) {
            float4 gb = s_g[g];
            float ltx = fmaxf(pb.x, gb.x), lty = fmaxf(pb.y, gb.y);
            float rbx = fminf(pb.z, gb.z), rby = fminf(pb.w, gb.w);
            float inter = fmaxf(rbx - ltx, 0.f) * fmaxf(rby - lty, 0.f);
            float uni = pa + s_ga[g] - inter;
            if (inter > 0.5f * fmaxf(uni, 1e-9f)) {
                any = true; ++tc;
                mc += r[s_gl[g]] - lse;
                float sl = 0.f, d, ad;
                d = pb.x - gb.x; ad = fabsf(d); sl += (ad < 1.f) ? 0.5f * d * d : ad - 0.5f;
                d = pb.y - gb.y; ad = fabsf(d); sl += (ad < 1.f) ? 0.5f * d * d : ad - 0.5f;
                d = pb.z - gb.z; ad = fabsf(d); sl += (ad < 1.f) ? 0.5f * d * d : ad - 0.5f;
                d = pb.w - gb.w; ad = fabsf(d); sl += (ad < 1.f) ? 0.5f * d * d : ad - 0.5f;
                lc += sl * 0.25f;
            }
        }

        float myneg = any ? 0.f : smmax;
        g_neg[row] = myneg;                              // coalesced STG.32
        atomicAdd(&g_hist[b * NBINH + val_bin(myneg)], 1u);

        warp_sum2(mc, lc);
        unsigned tcu = __reduce_add_sync(0xffffffffu, (unsigned)tc);
        if (lane == 0) { s_ra[warp] = mc; s_rb[warp] = lc; s_rt[warp] = (int)tcu; }
        __syncthreads();                                 // also frees buffer `cur`
        if (tid == 0) {
            float M = s_ra[0] + s_ra[1] + s_ra[2] + s_ra[3];
            float L = s_rb[0] + s_rb[1] + s_rb[2] + s_rb[3];
            int   T = s_rt[0] + s_rt[1] + s_rt[2] + s_rt[3];
            if (T) {
                atomicAdd(&g_pm[b], M);
                atomicAdd(&g_pl[b], L);
                atomicAdd(&g_pt[b], T);
            }
        }
        cur ^= 1;
        t = tn;
    }
    #undef CP_LOAD
}

// One 1024-thread block per image: histogram suffix-scan -> exact boundary bin
// + krem, one sweep of g_neg (bulk log1p + boundary collection), exact
// rank-select in the boundary bin, last-block final combine. Resets scratch.
__global__ __launch_bounds__(1024) void select_kernel(float* __restrict__ out)
{
    __shared__ unsigned s_wsum[32], s_wabove[32];
    __shared__ float    s_list[LIST_CAP];
    __shared__ unsigned s_cnt;
    __shared__ int      s_D;
    __shared__ unsigned s_krem;
    __shared__ float    s_red[32];
    __shared__ float    s_M, s_L;
    __shared__ int      s_k;
    __shared__ int      s_done;

    const int b = blockIdx.x, tid = threadIdx.x;
    const int lane = tid & 31, warp = tid >> 5;

    if (tid == 0) {
        float M = g_pm[b], L = g_pl[b];
        int   T = g_pt[b];
        s_M = M; s_L = L;
        int k = 3 * T;
        if (k > NP) k = NP;
        s_k = k;
        g_tot[b] = (float)T;
        g_pm[b] = 0.f; g_pl[b] = 0.f; g_pt[b] = 0;      // reset for next replay
        s_cnt = 0u; s_D = -1; s_krem = 0u;
    }
    __syncthreads();

    const unsigned k = (unsigned)s_k;
    unsigned* hist = g_hist + (size_t)b * NBINH;

    // per-thread chunk sum (16 bins), then block suffix-scan from the top
    unsigned part = 0u;
    {
        const uint4* hb = (const uint4*)hist;
        #pragma unroll
        for (int j = 0; j < BINS_PER_T / 4; ++j) {
            uint4 v = hb[tid * (BINS_PER_T / 4) + j];
            part += v.x + v.y + v.z + v.w;
        }
    }
    unsigned incl = part;                                // warp suffix-incl
    #pragma unroll
    for (int o = 1; o < 32; o <<= 1) {
        unsigned n = __shfl_down_sync(0xffffffffu, incl, o);
        if (lane + o < 32) incl += n;
    }
    if (lane == 0) s_wsum[warp] = incl;
    __syncthreads();
    if (warp == 0) {
        unsigned wv = s_wsum[lane];
        unsigned winc = wv;
        #pragma unroll
        for (int o = 1; o < 32; o <<= 1) {
            unsigned n = __shfl_down_sync(0xffffffffu, winc, o);
            if (lane + o < 32) winc += n;
        }
        s_wabove[lane] = winc - wv;                      // warps strictly above
    }
    __syncthreads();

    if (k > 0) {
        unsigned above = s_wabove[warp] + (incl - part);
        if (above < k && above + part >= k) {            // unique boundary chunk
            unsigned cum = above;
            int base = tid * BINS_PER_T;
            for (int j = BINS_PER_T - 1; j >= 0; --j) {
                unsigned c = hist[base + j];
                if (cum + c >= k) { s_D = base + j; s_krem = k - cum; break; }
                cum += c;
            }
        }
    }
    __syncthreads();

    const int      D    = s_D;
    const unsigned krem = s_krem;

    // reset own hist chunk (disjoint; only this thread read it)
    {
        uint4 z = make_uint4(0u, 0u, 0u, 0u);
        uint4* hw = (uint4*)hist;
        #pragma unroll
        for (int j = 0; j < BINS_PER_T / 4; ++j) hw[tid * (BINS_PER_T / 4) + j] = z;
    }

    // single sweep: bulk log1p for bins > D, collect boundary-bin values
    float local = 0.f;
    if (k > 0) {
        const float4* v4p = (const float4*)(g_neg + (size_t)b * NP);
        for (int i = tid; i < NP / 4; i += 1024) {
            float4 v4 = v4p[i];
            #pragma unroll
            for (int c = 0; c < 4; ++c) {
                float v = (c == 0) ? v4.x : (c == 1) ? v4.y : (c == 2) ? v4.z : v4.w;
                int bin = val_bin(v);
                if (bin > D) local += log1pf(v);
                else if (bin == D) {
                    unsigned idx = atomicAdd(&s_cnt, 1u);
                    if (idx < LIST_CAP) s_list[idx] = v;
                }
            }
        }
    }
    __syncthreads();

    // exact rank-select of krem largest within the boundary bin
    if (k > 0) {
        int L = (int)(s_cnt < LIST_CAP ? s_cnt : LIST_CAP);
        for (int j = tid; j < L; j += 1024) {
            float vj = s_list[j];
            int G = 0, E = 0;
            for (int i = 0; i < L; ++i) {
                float vi = s_list[i];
                G += (vi > vj);
                E += (vi == vj && i < j);
            }
            if ((unsigned)(G + E) < krem) local += log1pf(vj);
        }
    }

    local = warp_sum(local);
    if (lane == 0) s_red[warp] = local;
    __syncthreads();
    if (tid == 0) {
        float nm = 0.f;
        #pragma unroll
        for (int w = 0; w < 32; ++w) nm += s_red[w];
        g_res[b] = nm - s_M + s_L;
        __threadfence();
        unsigned old = atomicAdd(&g_ctr, 1u);
        s_done = (old == NB - 1) ? 1 : 0;
        if (s_done) g_ctr = 0u;                          // reset for next replay
    }
    __syncthreads();

    if (s_done && warp == 0) {
        __threadfence();
        float v = (lane < NB) ? g_res[lane] : 0.f;
        v = warp_sum(v);
        if (lane == 0) out[0] = v / g_tot[NB - 1];
    }
}

extern "C" void kernel_launch(void* const* d_in, const int* in_sizes, int n_in,
                              void* d_out, int out_size)
{
    const float4* pboxes = (const float4*)d_in[0];
    const float*  conf   = (const float*)d_in[1];
    const float4* gboxes = (const float4*)d_in[2];
    const int*    glab   = (const int*)d_in[3];

    // Unconditional (idempotent, capture-safe): 82944 B dynamic smem > default
    cudaFuncSetAttribute(main_kernel,
                         cudaFuncAttributeMaxDynamicSharedMemorySize,
                         2 * TILE_BYTES);

    main_kernel<<<GRID, TPB, 2 * TILE_BYTES>>>(pboxes, conf, gboxes, glab);
    select_kernel<<<NB, 1024>>>((float*)d_out);
}

// round 14
// speedup vs baseline: 1.5777x; 1.2001x over previous
#include <cuda_runtime.h>
#include <math.h>

#define NB 16
#define NP 32768
#define NG 32
#define NC 81
#define TPB 256                         // threads per main block (2 per row)
#define TILE_ROWS 128                   // rows per tile
#define TILE_FLOATS (TILE_ROWS * NC)    // 10368 floats
#define NTILES (NB * NP / TILE_ROWS)    // 4096
#define TILES_PER_IMG (NP / TILE_ROWS)  // 256
#define GRID 296                        // 2 blocks per SM on 148 SMs
#define TILE_F4 (TILE_FLOATS / 4)       // 2592 float4 per tile
#define TILE_BYTES (TILE_FLOATS * 4)    // 41472
#define NBINH 16384
#define BIN_BASE 0x3C000000             // float bits of 2^-7 (< 1/81)
#define BIN_SHIFT 12
#define LIST_CAP 2048
#define BINS_PER_T 16                   // bins/thread in 1024-thread select

// Scratch (device globals). All accumulators/counters self-reset each run.
__device__ float    g_neg[NB * NP];     // 0 if row matched, else sm_max
__device__ unsigned g_hist[NB * NBINH]; // per-image histogram
__device__ float    g_pm[NB];           // per-image matches_loss
__device__ float    g_pl[NB];           // per-image loc_loss
__device__ int      g_pt[NB];           // per-image total
__device__ float    g_res[NB];
__device__ float    g_tot[NB];
__device__ unsigned g_ctr = 0;

static __device__ __forceinline__ float warp_sum(float v) {
    #pragma unroll
    for (int o = 16; o; o >>= 1) v += __shfl_xor_sync(0xffffffffu, v, o);
    return v;
}
static __device__ __forceinline__ void warp_sum2(float& a, float& b) {
    #pragma unroll
    for (int o = 16; o; o >>= 1) {
        float aa = __shfl_xor_sync(0xffffffffu, a, o);
        float bb = __shfl_xor_sync(0xffffffffu, b, o);
        a += aa; b += bb;
    }
}
static __device__ __forceinline__ int val_bin(float v) {
    int bin = ((int)__float_as_uint(v) - BIN_BASE) >> BIN_SHIFT;
    return bin < 0 ? 0 : (bin > NBINH - 1 ? NBINH - 1 : bin);
}

// Double-buffered streaming main kernel, TWO THREADS PER ROW.
// 296 blocks grid-stride over 4096 tiles; cp.async prefetches tile t+GRID
// while tile t is computed. 256 threads/block -> 16 warps/SM (4/SMSP).
__global__ __launch_bounds__(TPB) void main_kernel(
    const float4* __restrict__ pboxes,   // (B,P,4)
    const float*  __restrict__ conf,     // (B,P,C)
    const float4* __restrict__ gboxes,   // (B,G,4)
    const int*    __restrict__ glab)     // (B,G)
{
    extern __shared__ float s_buf[];     // 2 * TILE_FLOATS floats = 82944 B
    __shared__ float4 s_g[NG];
    __shared__ float  s_ga[NG];
    __shared__ int    s_gl[NG];
    __shared__ float  s_ra[8], s_rb[8];
    __shared__ int    s_rt[8];

    const int tid  = threadIdx.x;
    const int lane = tid & 31, warp = tid >> 5;
    const int rp   = tid >> 1;           // row within tile (0..127)
    const int half = tid & 1;            // 0: cols 0..39 + 80, gt 0..15
                                         // 1: cols 40..79,     gt 16..31

    const unsigned sb0 = (unsigned)__cvta_generic_to_shared(s_buf);
    #define CP_LOAD(t, bufi)                                                    \
        do {                                                                    \
            const char* _src = (const char*)conf + (size_t)(t) * TILE_BYTES;    \
            unsigned _dst = sb0 + (bufi) * TILE_BYTES;                          \
            for (int _i = tid; _i < TILE_F4; _i += TPB)                         \
                asm volatile("cp.async.cg.shared.global [%0], [%1], 16;"        \
                             :: "r"(_dst + _i * 16), "l"(_src + (size_t)_i * 16)); \
            asm volatile("cp.async.commit_group;");                             \
        } while (0)

    int t   = blockIdx.x;
    int cur = 0;
    CP_LOAD(t, 0);

    while (t < NTILES) {
        const int tn = t + GRID;
        if (tn < NTILES) {
            CP_LOAD(tn, cur ^ 1);
            asm volatile("cp.async.wait_group 1;" ::: "memory");
        } else {
            asm volatile("cp.async.wait_group 0;" ::: "memory");
        }

        const int b = t / TILES_PER_IMG;
        if (tid < NG) {                  // (re)load gt data for this image
            float4 g = gboxes[b * NG + tid];
            s_g[tid]  = g;
            s_ga[tid] = fmaxf(g.z - g.x, 0.f) * fmaxf(g.w - g.y, 0.f);
            s_gl[tid] = glab[b * NG + tid];
        }
        __syncthreads();

        const float* r = s_buf + cur * TILE_FLOATS + rp * NC;
        const int cbase = half * 40;

        // raw-exp softmax stats over this thread's ~half row, 4-way ILP
        float s0 = 0.f, s1 = 0.f, s2 = 0.f, s3 = 0.f;
        float m0 = -1e30f, m1 = -1e30f, m2 = -1e30f, m3 = -1e30f;
        #pragma unroll
        for (int j = 0; j < 40; j += 4) {
            float x0 = r[cbase + j],     x1 = r[cbase + j + 1];
            float x2 = r[cbase + j + 2], x3 = r[cbase + j + 3];
            s0 += __expf(x0); s1 += __expf(x1); s2 += __expf(x2); s3 += __expf(x3);
            m0 = fmaxf(m0, x0); m1 = fmaxf(m1, x1);
            m2 = fmaxf(m2, x2); m3 = fmaxf(m3, x3);
        }
        if (!half) { float x = r[80]; s0 += __expf(x); m0 = fmaxf(m0, x); }
        float ssum = (s0 + s1) + (s2 + s3);
        float mmax = fmaxf(fmaxf(m0, m1), fmaxf(m2, m3));

        // pair combine (partner = lane^1)
        ssum += __shfl_xor_sync(0xffffffffu, ssum, 1);
        mmax = fmaxf(mmax, __shfl_xor_sync(0xffffffffu, mmax, 1));
        float lse   = __logf(ssum);
        float smmax = __fdividef(__expf(mmax), ssum);

        // IoU vs this thread's 16 gt boxes
        const int row = t * TILE_ROWS + rp;
        float4 pb = pboxes[row];
        float pa = fmaxf(pb.z - pb.x, 0.f) * fmaxf(pb.w - pb.y, 0.f);
        float mc = 0.f, lc = 0.f;
        int   tc = 0, anyi = 0;
        #pragma unroll 4
        for (int j = 0; j < 16; ++j) {
            int g = half * 16 + j;
            float4 gb = s_g[g];
            float ltx = fmaxf(pb.x, gb.x), lty = fmaxf(pb.y, gb.y);
            float rbx = fminf(pb.z, gb.z), rby = fminf(pb.w, gb.w);
            float inter = fmaxf(rbx - ltx, 0.f) * fmaxf(rby - lty, 0.f);
            float uni = pa + s_ga[g] - inter;
            if (inter > 0.5f * fmaxf(uni, 1e-9f)) {  // iou > 0.5, division-free
                anyi = 1; ++tc;
                mc += r[s_gl[g]] - lse;              // full row visible in smem
                float sl = 0.f, d, ad;
                d = pb.x - gb.x; ad = fabsf(d); sl += (ad < 1.f) ? 0.5f * d * d : ad - 0.5f;
                d = pb.y - gb.y; ad = fabsf(d); sl += (ad < 1.f) ? 0.5f * d * d : ad - 0.5f;
                d = pb.z - gb.z; ad = fabsf(d); sl += (ad < 1.f) ? 0.5f * d * d : ad - 0.5f;
                d = pb.w - gb.w; ad = fabsf(d); sl += (ad < 1.f) ? 0.5f * d * d : ad - 0.5f;
                lc += sl * 0.25f;
            }
        }
        // pair combine of match results
        mc  += __shfl_xor_sync(0xffffffffu, mc, 1);
        lc  += __shfl_xor_sync(0xffffffffu, lc, 1);
        tc  += __shfl_xor_sync(0xffffffffu, tc, 1);
        anyi |= __shfl_xor_sync(0xffffffffu, anyi, 1);

        float myneg = anyi ? 0.f : smmax;
        if (!half) {
            g_neg[row] = myneg;
            atomicAdd(&g_hist[b * NBINH + val_bin(myneg)], 1u);
            // keep pair totals once (even thread only) for the block reduce
        } else {
            mc = 0.f; lc = 0.f; tc = 0;
        }

        warp_sum2(mc, lc);
        unsigned tcu = __reduce_add_sync(0xffffffffu, (unsigned)tc);
        if (lane == 0) { s_ra[warp] = mc; s_rb[warp] = lc; s_rt[warp] = (int)tcu; }
        __syncthreads();                 // also frees buffer `cur`
        if (tid == 0) {
            float M = 0.f, L = 0.f; int T = 0;
            #pragma unroll
            for (int w = 0; w < 8; ++w) { M += s_ra[w]; L += s_rb[w]; T += s_rt[w]; }
            if (T) {
                atomicAdd(&g_pm[b], M);
                atomicAdd(&g_pl[b], L);
                atomicAdd(&g_pt[b], T);
            }
        }
        cur ^= 1;
        t = tn;
    }
    #undef CP_LOAD
}

// One 1024-thread block per image: histogram suffix-scan -> exact boundary bin
// + krem, one sweep of g_neg (bulk log1p + boundary collection), exact
// rank-select in the boundary bin, last-block final combine. Resets scratch.
__global__ __launch_bounds__(1024) void select_kernel(float* __restrict__ out)
{
    __shared__ unsigned s_wsum[32], s_wabove[32];
    __shared__ float    s_list[LIST_CAP];
    __shared__ unsigned s_cnt;
    __shared__ int      s_D;
    __shared__ unsigned s_krem;
    __shared__ float    s_red[32];
    __shared__ float    s_M, s_L;
    __shared__ int      s_k;
    __shared__ int      s_done;

    const int b = blockIdx.x, tid = threadIdx.x;
    const int lane = tid & 31, warp = tid >> 5;

    if (tid == 0) {
        float M = g_pm[b], L = g_pl[b];
        int   T = g_pt[b];
        s_M = M; s_L = L;
        int k = 3 * T;
        if (k > NP) k = NP;
        s_k = k;
        g_tot[b] = (float)T;
        g_pm[b] = 0.f; g_pl[b] = 0.f; g_pt[b] = 0;      // reset for next replay
        s_cnt = 0u; s_D = -1; s_krem = 0u;
    }
    __syncthreads();

    const unsigned k = (unsigned)s_k;
    unsigned* hist = g_hist + (size_t)b * NBINH;

    // per-thread chunk sum (16 bins), then block suffix-scan from the top
    unsigned part = 0u;
    {
        const uint4* hb = (const uint4*)hist;
        #pragma unroll
        for (int j = 0; j < BINS_PER_T / 4; ++j) {
            uint4 v = hb[tid * (BINS_PER_T / 4) + j];
            part += v.x + v.y + v.z + v.w;
        }
    }
    unsigned incl = part;                                // warp suffix-incl
    #pragma unroll
    for (int o = 1; o < 32; o <<= 1) {
        unsigned n = __shfl_down_sync(0xffffffffu, incl, o);
        if (lane + o < 32) incl += n;
    }
    if (lane == 0) s_wsum[warp] = incl;
    __syncthreads();
    if (warp == 0) {
        unsigned wv = s_wsum[lane];
        unsigned winc = wv;
        #pragma unroll
        for (int o = 1; o < 32; o <<= 1) {
            unsigned n = __shfl_down_sync(0xffffffffu, winc, o);
            if (lane + o < 32) winc += n;
        }
        s_wabove[lane] = winc - wv;                      // warps strictly above
    }
    __syncthreads();

    if (k > 0) {
        unsigned above = s_wabove[warp] + (incl - part);
        if (above < k && above + part >= k) {            // unique boundary chunk
            unsigned cum = above;
            int base = tid * BINS_PER_T;
            for (int j = BINS_PER_T - 1; j >= 0; --j) {
                unsigned c = hist[base + j];
                if (cum + c >= k) { s_D = base + j; s_krem = k - cum; break; }
                cum += c;
            }
        }
    }
    __syncthreads();

    const int      D    = s_D;
    const unsigned krem = s_krem;

    // reset own hist chunk (disjoint; only this thread read it)
    {
        uint4 z = make_uint4(0u, 0u, 0u, 0u);
        uint4* hw = (uint4*)hist;
        #pragma unroll
        for (int j = 0; j < BINS_PER_T / 4; ++j) hw[tid * (BINS_PER_T / 4) + j] = z;
    }

    // single sweep: bulk log1p for bins > D, collect boundary-bin values
    float local = 0.f;
    if (k > 0) {
        const float4* v4p = (const float4*)(g_neg + (size_t)b * NP);
        for (int i = tid; i < NP / 4; i += 1024) {
            float4 v4 = v4p[i];
            #pragma unroll
            for (int c = 0; c < 4; ++c) {
                float v = (c == 0) ? v4.x : (c == 1) ? v4.y : (c == 2) ? v4.z : v4.w;
                int bin = val_bin(v);
                if (bin > D) local += log1pf(v);
                else if (bin == D) {
                    unsigned idx = atomicAdd(&s_cnt, 1u);
                    if (idx < LIST_CAP) s_list[idx] = v;
                }
            }
        }
    }
    __syncthreads();

    // exact rank-select of krem largest within the boundary bin
    if (k > 0) {
        int L = (int)(s_cnt < LIST_CAP ? s_cnt : LIST_CAP);
        for (int j = tid; j < L; j += 1024) {
            float vj = s_list[j];
            int G = 0, E = 0;
            for (int i = 0; i < L; ++i) {
                float vi = s_list[i];
                G += (vi > vj);
                E += (vi == vj && i < j);
            }
            if ((unsigned)(G + E) < krem) local += log1pf(vj);
        }
    }

    local = warp_sum(local);
    if (lane == 0) s_red[warp] = local;
    __syncthreads();
    if (tid == 0) {
        float nm = 0.f;
        #pragma unroll
        for (int w = 0; w < 32; ++w) nm += s_red[w];
        g_res[b] = nm - s_M + s_L;
        __threadfence();
        unsigned old = atomicAdd(&g_ctr, 1u);
        s_done = (old == NB - 1) ? 1 : 0;
        if (s_done) g_ctr = 0u;                          // reset for next replay
    }
    __syncthreads();

    if (s_done && warp == 0) {
        __threadfence();
        float v = (lane < NB) ? g_res[lane] : 0.f;
        v = warp_sum(v);
        if (lane == 0) out[0] = v / g_tot[NB - 1];
    }
}

extern "C" void kernel_launch(void* const* d_in, const int* in_sizes, int n_in,
                              void* d_out, int out_size)
{
    const float4* pboxes = (const float4*)d_in[0];
    const float*  conf   = (const float*)d_in[1];
    const float4* gboxes = (const float4*)d_in[2];
    const int*    glab   = (const int*)d_in[3];

    // Unconditional (idempotent, capture-safe): 82944 B dynamic smem > default
    cudaFuncSetAttribute(main_kernel,
                         cudaFuncAttributeMaxDynamicSharedMemorySize,
                         2 * TILE_BYTES);

    main_kernel<<<GRID, TPB, 2 * TILE_BYTES>>>(pboxes, conf, gboxes, glab);
    select_kernel<<<NB, 1024>>>((float*)d_out);
}